// round 13
// baseline (speedup 1.0000x reference)
#include <cuda_runtime.h>

// ---------------- problem constants ----------------
#define C_CH   256
#define H_BEV  200
#define W_BEV  704
#define HW     (H_BEV * W_BEV)     // 140800
#define A_NUM  2
#define NC_NUM 4
#define K_SEL  20000
#define NSLOT  (A_NUM * HW)        // 281600 flat A*H*W cells
#define RM_OFF NSLOT               // rm starts after psm in d_out
#define NOUT16 16                  // 2 cls + 14 reg channels
#define PX_BLK 256                 // pixels per block
#define THREADS 256                // 2 halves x 128 (each thread: 2 px, 8 outs)
#define CHUNK  16                  // channels per pipeline stage
#define NCHUNK (C_CH / CHUNK)      // 16

// packed winner table: high32 = float bits of peer score (positive -> monotonic),
// low32 = ((3 - cav_idx) << 16) | k.  0 == no peer selected this cell.
__device__ __align__(16) unsigned long long g_slots[NSLOT];

// ---------------- f32x2 helpers ----------------
__device__ __forceinline__ unsigned long long pack2(float lo, float hi) {
    unsigned long long r;
    asm("mov.b64 %0, {%1, %2};" : "=l"(r) : "f"(lo), "f"(hi));
    return r;
}
__device__ __forceinline__ void unpack2(unsigned long long v, float& lo, float& hi) {
    asm("mov.b64 {%0, %1}, %2;" : "=f"(lo), "=f"(hi) : "l"(v));
}
__device__ __forceinline__ unsigned long long fma2(unsigned long long a,
                                                   unsigned long long b,
                                                   unsigned long long c) {
    asm("fma.rn.f32x2 %0, %1, %2, %3;" : "=l"(c) : "l"(a), "l"(b), "l"(c));
    return c;
}
__device__ __forceinline__ void cp_async16(unsigned smem_dst, const void* gsrc) {
    asm volatile("cp.async.cg.shared.global [%0], [%1], 16;\n"
                 :: "r"(smem_dst), "l"(gsrc));
}

// ---------------- kernel 1: scatter peer candidates ----------------
__global__ void k_scatter(const int* __restrict__ mask_idx,
                          const float* __restrict__ scores) {
    int t = blockIdx.x * blockDim.x + threadIdx.x;
    if (t >= NC_NUM * K_SEL) return;
    int i = t / K_SEL;
    int k = t - i * K_SEL;                       // k < 20000 < 2^16
    int f = mask_idx[t];                         // flat index in [0, A*H*W)
    unsigned long long key =
        ((unsigned long long)__float_as_uint(scores[t]) << 32) |
        ((unsigned long long)(3 - i) << 16) | (unsigned)k;
    atomicMax(&g_slots[f], key);
}

// ---------------- kernel 2: cp.async pipeline + output-split halves --------
// 256 threads = 2 output-halves x 128 pixel-pairs. 550 blocks exactly.
__global__ __launch_bounds__(THREADS)
void k_main(const float*  __restrict__ feat,     // [C, HW] f32
            const float*  __restrict__ cls_w,    // [2, 256]
            const float*  __restrict__ cls_b,    // [2]
            const float*  __restrict__ reg_w,    // [14, 256]
            const float*  __restrict__ reg_b,    // [14]
            const float*  __restrict__ psm_v2x,  // [4, 20000]
            const float*  __restrict__ rm_v2x,   // [4, 7*20000]
            float*        __restrict__ out) {    // [psm 281600 | rm 1971200]
    // weights stored once as f32x2 output-pairs: w2v[c][g].x = (w_{4g},w_{4g+1}),
    // .y = (w_{4g+2},w_{4g+3}).  Half h uses g = 2h, 2h+1.
    __shared__ __align__(16) ulonglong2 w2v[C_CH][NOUT16 / 4];   // 16384 B
    __shared__ __align__(16) float fbuf[2][CHUNK][PX_BLK];       // 32768 B
    // winner decisions, written by half 0: bit31=peer, bits16..17=ci, low16=ck
    __shared__ unsigned dec[A_NUM][PX_BLK];                      // 2048 B

    const int tid    = threadIdx.x;
    const int pxBase = blockIdx.x * PX_BLK;
    const int lane64 = tid & 63;          // 16B segment within a 1KB row
    const int rrow   = tid >> 6;          // starting row (0..3), stride 4
    const int half   = tid >> 7;          // output half 0/1
    const int pi     = tid & 127;         // pixel-pair slot: px 2pi, 2pi+1

    unsigned fbuf_s = (unsigned)__cvta_generic_to_shared(&fbuf[0][0][0]);

    // ---- prologue: start chunks 0 and 1 flying first ----
#pragma unroll
    for (int b = 0; b < 2; ++b) {
        for (int r = rrow; r < CHUNK; r += 4)
            cp_async16(fbuf_s + (unsigned)(b * CHUNK + r) * (PX_BLK * 4) + lane64 * 16,
                       feat + (size_t)(b * CHUNK + r) * HW + pxBase + lane64 * 4);
        asm volatile("cp.async.commit_group;\n");
    }

    // ---- weight fill overlaps with the first copies ----
    for (int idx = tid; idx < C_CH * (NOUT16 / 2); idx += THREADS) {
        int c = idx >> 3, h = idx & 7;           // h = output-pair index 0..7
        int o0 = 2 * h, o1 = 2 * h + 1;
        float w0 = (o0 < A_NUM) ? cls_w[o0 * C_CH + c] : reg_w[(o0 - A_NUM) * C_CH + c];
        float w1 = (o1 < A_NUM) ? cls_w[o1 * C_CH + c] : reg_w[(o1 - A_NUM) * C_CH + c];
        ((unsigned long long*)&w2v[c][0])[h] = pack2(w0, w1);
    }

    // 4 output-pairs (this half's 8 outputs) x 2 pixels
    unsigned long long a0[4], a1[4];
#pragma unroll
    for (int h = 0; h < 4; ++h) { a0[h] = 0ULL; a1[h] = 0ULL; }

    // ---- main pipeline: compute chunk k, copy chunk k+2 ----
    for (int k = 0; k < NCHUNK; ++k) {
        int buf = k & 1;
        asm volatile("cp.async.wait_group 1;\n");   // chunk k landed
        __syncthreads();

        const ulonglong2* wp = &w2v[k * CHUNK][2 * half];
#pragma unroll
        for (int c = 0; c < CHUNK; ++c) {
            float2 x = *(const float2*)&fbuf[buf][c][2 * pi];  // LDS.64, 0-conflict
            unsigned long long xs0 = pack2(x.x, x.x);
            unsigned long long xs1 = pack2(x.y, x.y);
            ulonglong2 wA = wp[0];                             // broadcast LDS.128
            ulonglong2 wB = wp[1];
            a0[0] = fma2(xs0, wA.x, a0[0]);
            a0[1] = fma2(xs0, wA.y, a0[1]);
            a0[2] = fma2(xs0, wB.x, a0[2]);
            a0[3] = fma2(xs0, wB.y, a0[3]);
            a1[0] = fma2(xs1, wA.x, a1[0]);
            a1[1] = fma2(xs1, wA.y, a1[1]);
            a1[2] = fma2(xs1, wB.x, a1[2]);
            a1[3] = fma2(xs1, wB.y, a1[3]);
            wp += NOUT16 / 4;
        }
        __syncthreads();                 // everyone done reading buf before reuse

        int nk = k + 2;
        if (nk < NCHUNK) {
            for (int r = rrow; r < CHUNK; r += 4)
                cp_async16(fbuf_s + (unsigned)(buf * CHUNK + r) * (PX_BLK * 4) + lane64 * 16,
                           feat + (size_t)(nk * CHUNK + r) * HW + pxBase + lane64 * 4);
        }
        asm volatile("cp.async.commit_group;\n");   // keep group count in step
    }

    // local outputs: half 0 -> global 0..7 (cls0,cls1, reg 0..5)
    //                half 1 -> global 8..15 (reg 6..13)
    float v[8][2];
#pragma unroll
    for (int h = 0; h < 4; ++h) {
        unpack2(a0[h], v[2 * h][0], v[2 * h + 1][0]);
        unpack2(a1[h], v[2 * h][1], v[2 * h + 1][1]);
    }

    int p = pxBase + 2 * pi;

    if (half == 0) {
        // decide winners for both anchors; publish + write psm
#pragma unroll
        for (int a = 0; a < A_NUM; ++a) {
            float cb = cls_b[a];
            ulonglong2 keys = *(const ulonglong2*)&g_slots[a * HW + p];
            float psm_o[2];
#pragma unroll
            for (int j = 0; j < 2; ++j) {
                float psm_ego = v[a][j] + cb;
                float prob    = 1.0f / (1.0f + expf(-psm_ego));  // sigmoid, fp32
                unsigned long long key = (j == 0) ? keys.x : keys.y;
                unsigned d = 0;
                float pv = psm_ego;
                if (key != 0ULL) {
                    float s = __uint_as_float((unsigned)(key >> 32));
                    if (s > prob) {          // strict >: ego wins ties (argmax first-max)
                        unsigned lo = (unsigned)key;
                        int ck = (int)(lo & 0xFFFFu);
                        int ci = 3 - (int)((lo >> 16) & 0xFFFFu);
                        d = 0x80000000u | ((unsigned)ci << 16) | (unsigned)ck;
                        pv = psm_v2x[ci * K_SEL + ck];
                    }
                }
                dec[a][2 * pi + j] = d;
                psm_o[j] = pv;
            }
            *(float2*)&out[a * HW + p] = make_float2(psm_o[0], psm_o[1]);
        }
    }
    __syncthreads();

    // reg outputs: half 0 -> rc 0..5 (local o 2..7), half 1 -> rc 6..13 (local o 0..7)
    const int nrc    = (half == 0) ? 6 : 8;
    const int rcBase = (half == 0) ? 0 : 6;
    const int loBase = (half == 0) ? 2 : 0;
#pragma unroll 8
    for (int lr = 0; lr < nrc; ++lr) {
        int rc = rcBase + lr;
        int lo = loBase + lr;
        int a  = rc & 1, r = rc >> 1;
        float rb = reg_b[rc];
        float o2[2];
#pragma unroll
        for (int j = 0; j < 2; ++j) {
            unsigned d = dec[a][2 * pi + j];
            if (d & 0x80000000u) {
                int ci = (int)((d >> 16) & 0x3u);
                int ck = (int)(d & 0xFFFFu);
                o2[j] = rm_v2x[(ci * 7 + r) * K_SEL + ck];
            } else {
                o2[j] = v[lo][j] + rb;
            }
        }
        *(float2*)&out[RM_OFF + rc * HW + p] = make_float2(o2[0], o2[1]);
    }
}

// ---------------- launch ----------------
extern "C" void kernel_launch(void* const* d_in, const int* in_sizes, int n_in,
                              void* d_out, int out_size) {
    const float*  feat     = (const float*)d_in[0];   // [1,256,200,704] f32
    const float*  cls_w    = (const float*)d_in[1];   // [2,256]
    const float*  cls_b    = (const float*)d_in[2];   // [2]
    const float*  reg_w    = (const float*)d_in[3];   // [14,256]
    const float*  reg_b    = (const float*)d_in[4];   // [14]
    const float*  psm_v2x  = (const float*)d_in[5];   // [4,20000]
    const float*  rm_v2x   = (const float*)d_in[6];   // [4,140000]
    const float*  scores   = (const float*)d_in[7];   // [4,20000]
    const int*    mask_idx = (const int*)d_in[8];     // [4,20000]
    // d_in[9] = mask_reg_idx: derivable (f + r*A*H*W), unused.
    float* out = (float*)d_out;

    // zero the winner table via a graph memset node (no kernel launch cost)
    void* slots_ptr = nullptr;
    cudaGetSymbolAddress(&slots_ptr, g_slots);
    cudaMemsetAsync(slots_ptr, 0, NSLOT * sizeof(unsigned long long));

    k_scatter<<<(NC_NUM * K_SEL + 255) / 256, 256>>>(mask_idx, scores);

    k_main<<<HW / PX_BLK, THREADS>>>(feat, cls_w, cls_b, reg_w, reg_b,
                                     psm_v2x, rm_v2x, out);
}

// round 14
// speedup vs baseline: 1.1277x; 1.1277x over previous
#include <cuda_runtime.h>

// ---------------- problem constants ----------------
#define C_CH   256
#define H_BEV  200
#define W_BEV  704
#define HW     (H_BEV * W_BEV)     // 140800
#define A_NUM  2
#define NC_NUM 4
#define K_SEL  20000
#define NSLOT  (A_NUM * HW)        // 281600 flat A*H*W cells
#define RM_OFF NSLOT               // rm starts after psm in d_out
#define NOUT16 16                  // 2 cls + 14 reg channels
#define PX_BLK 256                 // pixels per block
#define THREADS 256                // 128 pixel-pairs x 2 channel-halves
#define CHUNK  16                  // channels per pipeline stage
#define CHALF  8                   // channels per half per stage
#define NCHUNK (C_CH / CHUNK)      // 16

// packed winner table: high32 = float bits of peer score (positive -> monotonic),
// low32 = ((3 - cav_idx) << 16) | k.  0 == no peer selected this cell.
__device__ __align__(16) unsigned long long g_slots[NSLOT];

// ---------------- f32x2 helpers ----------------
__device__ __forceinline__ unsigned long long pack2(float lo, float hi) {
    unsigned long long r;
    asm("mov.b64 %0, {%1, %2};" : "=l"(r) : "f"(lo), "f"(hi));
    return r;
}
__device__ __forceinline__ void unpack2(unsigned long long v, float& lo, float& hi) {
    asm("mov.b64 {%0, %1}, %2;" : "=f"(lo), "=f"(hi) : "l"(v));
}
__device__ __forceinline__ unsigned long long fma2(unsigned long long a,
                                                   unsigned long long b,
                                                   unsigned long long c) {
    asm("fma.rn.f32x2 %0, %1, %2, %3;" : "=l"(c) : "l"(a), "l"(b), "l"(c));
    return c;
}
__device__ __forceinline__ unsigned long long add2(unsigned long long a,
                                                   unsigned long long b) {
    unsigned long long r;
    asm("add.rn.f32x2 %0, %1, %2;" : "=l"(r) : "l"(a), "l"(b));
    return r;
}
__device__ __forceinline__ void cp_async16(unsigned smem_dst, const void* gsrc) {
    asm volatile("cp.async.cg.shared.global [%0], [%1], 16;\n"
                 :: "r"(smem_dst), "l"(gsrc));
}

// ---------------- kernel 1: scatter peer candidates ----------------
__global__ void k_scatter(const int* __restrict__ mask_idx,
                          const float* __restrict__ scores) {
    int t = blockIdx.x * blockDim.x + threadIdx.x;
    if (t >= NC_NUM * K_SEL) return;
    int i = t / K_SEL;
    int k = t - i * K_SEL;                       // k < 20000 < 2^16
    int f = mask_idx[t];                         // flat index in [0, A*H*W)
    unsigned long long key =
        ((unsigned long long)__float_as_uint(scores[t]) << 32) |
        ((unsigned long long)(3 - i) << 16) | (unsigned)k;
    atomicMax(&g_slots[f], key);
}

// ---------------- kernel 2: cp.async pipeline + in-chunk split-K=2 ---------
// 256 threads = 128 pixel-pairs x 2 channel-halves. 550 blocks exactly.
__global__ __launch_bounds__(THREADS)
void k_main(const float*  __restrict__ feat,     // [C, HW] f32
            const float*  __restrict__ cls_w,    // [2, 256]
            const float*  __restrict__ cls_b,    // [2]
            const float*  __restrict__ reg_w,    // [14, 256]
            const float*  __restrict__ reg_b,    // [14]
            const float*  __restrict__ psm_v2x,  // [4, 20000]
            const float*  __restrict__ rm_v2x,   // [4, 7*20000]
            float*        __restrict__ out) {    // [psm 281600 | rm 1971200]
    // weights stored once as f32x2 output-pairs: w2v[c][g].x = (w_{4g},w_{4g+1}),
    // .y = (w_{4g+2},w_{4g+3}).  One broadcast LDS.128 feeds 4 outputs.
    __shared__ __align__(16) ulonglong2 w2v[C_CH][NOUT16 / 4];   // 16384 B
    __shared__ __align__(16) float fbuf[2][CHUNK][PX_BLK];       // 32768 B
    // total static smem = 49152 B; fbuf reused for split-K reduction (16 KB)

    const int tid    = threadIdx.x;
    const int pxBase = blockIdx.x * PX_BLK;
    const int lane64 = tid & 63;          // 16B segment within a 1KB row
    const int rrow   = tid >> 6;          // starting row (0..3), stride 4
    const int half   = tid >> 7;          // channel half within each chunk
    const int pi     = tid & 127;         // pixel-pair slot: px 2pi, 2pi+1

    unsigned fbuf_s = (unsigned)__cvta_generic_to_shared(&fbuf[0][0][0]);

    // ---- prologue: start chunks 0 and 1 flying first ----
#pragma unroll
    for (int b = 0; b < 2; ++b) {
        for (int r = rrow; r < CHUNK; r += 4)
            cp_async16(fbuf_s + (unsigned)(b * CHUNK + r) * (PX_BLK * 4) + lane64 * 16,
                       feat + (size_t)(b * CHUNK + r) * HW + pxBase + lane64 * 4);
        asm volatile("cp.async.commit_group;\n");
    }

    // ---- weight fill overlaps with the first copies ----
    for (int idx = tid; idx < C_CH * (NOUT16 / 2); idx += THREADS) {
        int c = idx >> 3, h = idx & 7;           // h = output-pair index 0..7
        int o0 = 2 * h, o1 = 2 * h + 1;
        float w0 = (o0 < A_NUM) ? cls_w[o0 * C_CH + c] : reg_w[(o0 - A_NUM) * C_CH + c];
        float w1 = (o1 < A_NUM) ? cls_w[o1 * C_CH + c] : reg_w[(o1 - A_NUM) * C_CH + c];
        ((unsigned long long*)&w2v[c][0])[h] = pack2(w0, w1);
    }

    // all 16 outputs (8 f32x2 pairs) x 2 pixels; each half covers 128 channels
    unsigned long long a0[NOUT16 / 2], a1[NOUT16 / 2];
#pragma unroll
    for (int h = 0; h < NOUT16 / 2; ++h) { a0[h] = 0ULL; a1[h] = 0ULL; }

    // ---- main pipeline: compute my half of chunk k, copy chunk k+2 ----
    for (int k = 0; k < NCHUNK; ++k) {
        int buf = k & 1;
        asm volatile("cp.async.wait_group 1;\n");   // chunk k landed
        __syncthreads();

        const ulonglong2* wp = &w2v[k * CHUNK + half * CHALF][0];
        const float* fb = &fbuf[buf][half * CHALF][0];
#pragma unroll
        for (int c = 0; c < CHALF; ++c) {
            float2 x = *(const float2*)&fb[c * PX_BLK + 2 * pi]; // LDS.64, 0-conflict
            unsigned long long xs0 = pack2(x.x, x.x);
            unsigned long long xs1 = pack2(x.y, x.y);
#pragma unroll
            for (int g = 0; g < NOUT16 / 4; ++g) {
                ulonglong2 w = wp[g];                            // broadcast LDS.128
                a0[2 * g]     = fma2(xs0, w.x, a0[2 * g]);
                a0[2 * g + 1] = fma2(xs0, w.y, a0[2 * g + 1]);
                a1[2 * g]     = fma2(xs1, w.x, a1[2 * g]);
                a1[2 * g + 1] = fma2(xs1, w.y, a1[2 * g + 1]);
            }
            wp += NOUT16 / 4;
        }
        __syncthreads();                 // everyone done reading buf before reuse

        int nk = k + 2;
        if (nk < NCHUNK) {
            for (int r = rrow; r < CHUNK; r += 4)
                cp_async16(fbuf_s + (unsigned)(buf * CHUNK + r) * (PX_BLK * 4) + lane64 * 16,
                           feat + (size_t)(nk * CHUNK + r) * HW + pxBase + lane64 * 4);
        }
        asm volatile("cp.async.commit_group;\n");   // keep group count in step
    }

    // ---- split-K reduction: half 1 publishes into fbuf space, half 0 adds ----
    unsigned long long* red = (unsigned long long*)&fbuf[0][0][0];  // 16 KB reuse
    if (half == 1) {
#pragma unroll
        for (int h = 0; h < NOUT16 / 2; ++h) {
            red[h * 128 + pi]                     = a0[h];   // STS.64 conflict-free
            red[(NOUT16 / 2 + h) * 128 + pi]      = a1[h];
        }
    }
    __syncthreads();
    if (half == 1) return;

#pragma unroll
    for (int h = 0; h < NOUT16 / 2; ++h) {
        a0[h] = add2(a0[h], red[h * 128 + pi]);
        a1[h] = add2(a1[h], red[(NOUT16 / 2 + h) * 128 + pi]);
    }

    float v[NOUT16][2];
#pragma unroll
    for (int h = 0; h < NOUT16 / 2; ++h) {
        unpack2(a0[h], v[2 * h][0], v[2 * h + 1][0]);
        unpack2(a1[h], v[2 * h][1], v[2 * h + 1][1]);
    }

    int p = pxBase + 2 * pi;
#pragma unroll
    for (int a = 0; a < A_NUM; ++a) {
        float cb = cls_b[a];
        // slot pair for this anchor's two pixels (16B aligned: p even)
        ulonglong2 keys = *(const ulonglong2*)&g_slots[a * HW + p];

        bool  peer[2];
        int   ci[2], ck[2];
        float psm_o[2];
#pragma unroll
        for (int j = 0; j < 2; ++j) {
            float psm_ego = v[a][j] + cb;
            float prob    = 1.0f / (1.0f + expf(-psm_ego));  // sigmoid, fp32
            unsigned long long key = (j == 0) ? keys.x : keys.y;
            peer[j] = false; ci[j] = 0; ck[j] = 0;
            if (key != 0ULL) {
                float s = __uint_as_float((unsigned)(key >> 32));
                if (s > prob) {              // strict >: ego wins ties (argmax first-max)
                    peer[j] = true;
                    unsigned lo = (unsigned)key;
                    ck[j] = (int)(lo & 0xFFFFu);
                    ci[j] = 3 - (int)((lo >> 16) & 0xFFFFu);
                }
            }
            psm_o[j] = peer[j] ? psm_v2x[ci[j] * K_SEL + ck[j]] : psm_ego;
        }
        *(float2*)&out[a * HW + p] = make_float2(psm_o[0], psm_o[1]);

#pragma unroll
        for (int r = 0; r < 7; ++r) {
            int rc = 2 * r + a;              // rm channel using anchor-a winner
            float rb = reg_b[rc];
            float r0 = peer[0] ? rm_v2x[(ci[0] * 7 + r) * K_SEL + ck[0]]
                               : v[A_NUM + rc][0] + rb;
            float r1 = peer[1] ? rm_v2x[(ci[1] * 7 + r) * K_SEL + ck[1]]
                               : v[A_NUM + rc][1] + rb;
            *(float2*)&out[RM_OFF + rc * HW + p] = make_float2(r0, r1);
        }
    }
}

// ---------------- launch ----------------
extern "C" void kernel_launch(void* const* d_in, const int* in_sizes, int n_in,
                              void* d_out, int out_size) {
    const float*  feat     = (const float*)d_in[0];   // [1,256,200,704] f32
    const float*  cls_w    = (const float*)d_in[1];   // [2,256]
    const float*  cls_b    = (const float*)d_in[2];   // [2]
    const float*  reg_w    = (const float*)d_in[3];   // [14,256]
    const float*  reg_b    = (const float*)d_in[4];   // [14]
    const float*  psm_v2x  = (const float*)d_in[5];   // [4,20000]
    const float*  rm_v2x   = (const float*)d_in[6];   // [4,140000]
    const float*  scores   = (const float*)d_in[7];   // [4,20000]
    const int*    mask_idx = (const int*)d_in[8];     // [4,20000]
    // d_in[9] = mask_reg_idx: derivable (f + r*A*H*W), unused.
    float* out = (float*)d_out;

    // zero the winner table via a graph memset node (no kernel launch cost)
    void* slots_ptr = nullptr;
    cudaGetSymbolAddress(&slots_ptr, g_slots);
    cudaMemsetAsync(slots_ptr, 0, NSLOT * sizeof(unsigned long long));

    k_scatter<<<(NC_NUM * K_SEL + 255) / 256, 256>>>(mask_idx, scores);

    k_main<<<HW / PX_BLK, THREADS>>>(feat, cls_w, cls_b, reg_w, reg_b,
                                     psm_v2x, rm_v2x, out);
}

// round 15
// speedup vs baseline: 1.1691x; 1.0367x over previous
#include <cuda_runtime.h>

// ---------------- problem constants ----------------
#define C_CH   256
#define H_BEV  200
#define W_BEV  704
#define HW     (H_BEV * W_BEV)     // 140800
#define A_NUM  2
#define NC_NUM 4
#define K_SEL  20000
#define NSLOT  (A_NUM * HW)        // 281600 flat A*H*W cells
#define RM_OFF NSLOT               // rm starts after psm in d_out
#define NOUT16 16                  // 2 cls + 14 reg channels
#define PX_BLK 256                 // pixels per block
#define THREADS 128                // 2 px per thread
#define CHUNK  8                   // channels per pipeline stage
#define NSTAGE 4                   // pipeline depth
#define NCHUNK (C_CH / CHUNK)      // 32
#define STAGE_BYTES (CHUNK * PX_BLK * 4)   // 8192

// packed winner table: high32 = float bits of peer score (positive -> monotonic),
// low32 = ((3 - cav_idx) << 16) | k.  0 == no peer selected this cell.
__device__ __align__(16) unsigned long long g_slots[NSLOT];

// ---------------- f32x2 helpers ----------------
__device__ __forceinline__ unsigned long long pack2(float lo, float hi) {
    unsigned long long r;
    asm("mov.b64 %0, {%1, %2};" : "=l"(r) : "f"(lo), "f"(hi));
    return r;
}
__device__ __forceinline__ void unpack2(unsigned long long v, float& lo, float& hi) {
    asm("mov.b64 {%0, %1}, %2;" : "=f"(lo), "=f"(hi) : "l"(v));
}
__device__ __forceinline__ unsigned long long fma2(unsigned long long a,
                                                   unsigned long long b,
                                                   unsigned long long c) {
    asm("fma.rn.f32x2 %0, %1, %2, %3;" : "=l"(c) : "l"(a), "l"(b), "l"(c));
    return c;
}
__device__ __forceinline__ void cp_async16(unsigned smem_dst, const void* gsrc) {
    asm volatile("cp.async.cg.shared.global [%0], [%1], 16;\n"
                 :: "r"(smem_dst), "l"(gsrc));
}

// ---------------- kernel 1: scatter peer candidates ----------------
__global__ void k_scatter(const int* __restrict__ mask_idx,
                          const float* __restrict__ scores) {
    int t = blockIdx.x * blockDim.x + threadIdx.x;
    if (t >= NC_NUM * K_SEL) return;
    int i = t / K_SEL;
    int k = t - i * K_SEL;                       // k < 20000 < 2^16
    int f = mask_idx[t];                         // flat index in [0, A*H*W)
    unsigned long long key =
        ((unsigned long long)__float_as_uint(scores[t]) << 32) |
        ((unsigned long long)(3 - i) << 16) | (unsigned)k;
    atomicMax(&g_slots[f], key);
}

// ---------------- kernel 2: 4-stage cp.async pipeline, 1 barrier/chunk -----
// 128 threads x 2 px = 256 pixels per block; grid = 550 exactly.
__global__ __launch_bounds__(THREADS)
void k_main(const float*  __restrict__ feat,     // [C, HW] f32
            const float*  __restrict__ cls_w,    // [2, 256]
            const float*  __restrict__ cls_b,    // [2]
            const float*  __restrict__ reg_w,    // [14, 256]
            const float*  __restrict__ reg_b,    // [14]
            const float*  __restrict__ psm_v2x,  // [4, 20000]
            const float*  __restrict__ rm_v2x,   // [4, 7*20000]
            float*        __restrict__ out) {    // [psm 281600 | rm 1971200]
    // weights stored once as f32x2 output-pairs: w2v[c][g].x = (w_{4g},w_{4g+1}),
    // .y = (w_{4g+2},w_{4g+3}).  One LDS.128 feeds 4 outputs.
    __shared__ __align__(16) ulonglong2 w2v[C_CH][NOUT16 / 4];       // 16384 B
    __shared__ __align__(16) float fbuf[NSTAGE][CHUNK][PX_BLK];      // 32768 B
    // total static smem = 49152 B

    const int tid    = threadIdx.x;
    const int pxBase = blockIdx.x * PX_BLK;
    const int lane64 = tid & 63;          // 16B segment within a 1KB row
    const int r0     = tid >> 6;          // starting row (0/1); rows r0,r0+2,r0+4,r0+6
    const int pi     = tid;               // pixel-pair slot: px 2pi, 2pi+1

    unsigned fbuf_s = (unsigned)__cvta_generic_to_shared(&fbuf[0][0][0]);
    const unsigned my_dst0 = fbuf_s + (unsigned)r0 * (PX_BLK * 4) + lane64 * 16;
    const float*   my_src0 = feat + (size_t)r0 * HW + pxBase + lane64 * 4;

    // ---- prologue: launch chunks 0..2 into slots 0..2 ----
#pragma unroll
    for (int b = 0; b < NSTAGE - 1; ++b) {
#pragma unroll
        for (int rr = 0; rr < 4; ++rr)       // rows r0 + 2*rr
            cp_async16(my_dst0 + (unsigned)b * STAGE_BYTES + (unsigned)(2 * rr) * (PX_BLK * 4),
                       my_src0 + (size_t)(b * CHUNK + 2 * rr) * HW);
        asm volatile("cp.async.commit_group;\n");
    }

    // ---- weight fill overlaps with the first copies ----
    for (int idx = tid; idx < C_CH * (NOUT16 / 2); idx += THREADS) {
        int c = idx >> 3, h = idx & 7;           // h = output-pair index 0..7
        int o0 = 2 * h, o1 = 2 * h + 1;
        float w0 = (o0 < A_NUM) ? cls_w[o0 * C_CH + c] : reg_w[(o0 - A_NUM) * C_CH + c];
        float w1 = (o1 < A_NUM) ? cls_w[o1 * C_CH + c] : reg_w[(o1 - A_NUM) * C_CH + c];
        ((unsigned long long*)&w2v[c][0])[h] = pack2(w0, w1);
    }

    unsigned long long a0[NOUT16 / 2], a1[NOUT16 / 2];   // per-pixel accs
#pragma unroll
    for (int h = 0; h < NOUT16 / 2; ++h) { a0[h] = 0ULL; a1[h] = 0ULL; }

    // running source pointer for the look-ahead chunk (k+3)
    const float* srcNext = my_src0 + (size_t)(NSTAGE - 1) * CHUNK * HW;

    // ---- main loop: wait chunk k, barrier, issue chunk k+3, compute k ----
    for (int k = 0; k < NCHUNK; ++k) {
        asm volatile("cp.async.wait_group %0;\n" :: "n"(NSTAGE - 2));
        __syncthreads();                    // chunk k visible to all threads

        // issue copies for chunk k+3 into slot (k+3)&3 == (k-1)&3 (consumed
        // at iter k-1; everyone is past it because they passed this barrier)
        if (k + NSTAGE - 1 < NCHUNK) {
            unsigned dst = my_dst0 + (unsigned)((k + NSTAGE - 1) & (NSTAGE - 1)) * STAGE_BYTES;
#pragma unroll
            for (int rr = 0; rr < 4; ++rr)
                cp_async16(dst + (unsigned)(2 * rr) * (PX_BLK * 4),
                           srcNext + (size_t)(2 * rr) * HW);
            srcNext += (size_t)CHUNK * HW;
        }
        asm volatile("cp.async.commit_group;\n");   // keep group count in step

        const ulonglong2* wp = &w2v[k * CHUNK][0];
        const float* fb = &fbuf[k & (NSTAGE - 1)][0][0];
#pragma unroll
        for (int c = 0; c < CHUNK; ++c) {
            float2 x = *(const float2*)&fb[c * PX_BLK + 2 * pi]; // LDS.64, 0-conflict
            unsigned long long xs0 = pack2(x.x, x.x);
            unsigned long long xs1 = pack2(x.y, x.y);
#pragma unroll
            for (int g = 0; g < NOUT16 / 4; ++g) {
                ulonglong2 w = wp[g];                            // LDS.128
                a0[2 * g]     = fma2(xs0, w.x, a0[2 * g]);
                a0[2 * g + 1] = fma2(xs0, w.y, a0[2 * g + 1]);
                a1[2 * g]     = fma2(xs1, w.x, a1[2 * g]);
                a1[2 * g + 1] = fma2(xs1, w.y, a1[2 * g + 1]);
            }
            wp += NOUT16 / 4;
        }
        // no second barrier: the slot written next iteration was consumed
        // one full iteration earlier.
    }

    float v[NOUT16][2];
#pragma unroll
    for (int h = 0; h < NOUT16 / 2; ++h) {
        unpack2(a0[h], v[2 * h][0], v[2 * h + 1][0]);
        unpack2(a1[h], v[2 * h][1], v[2 * h + 1][1]);
    }

    int p = pxBase + 2 * pi;
#pragma unroll
    for (int a = 0; a < A_NUM; ++a) {
        float cb = cls_b[a];
        // slot pair for this anchor's two pixels (16B aligned: p even)
        ulonglong2 keys = *(const ulonglong2*)&g_slots[a * HW + p];

        bool  peer[2];
        int   ci[2], ck[2];
        float psm_o[2];
#pragma unroll
        for (int j = 0; j < 2; ++j) {
            float psm_ego = v[a][j] + cb;
            float prob    = 1.0f / (1.0f + expf(-psm_ego));  // sigmoid, fp32
            unsigned long long key = (j == 0) ? keys.x : keys.y;
            peer[j] = false; ci[j] = 0; ck[j] = 0;
            if (key != 0ULL) {
                float s = __uint_as_float((unsigned)(key >> 32));
                if (s > prob) {              // strict >: ego wins ties (argmax first-max)
                    peer[j] = true;
                    unsigned lo = (unsigned)key;
                    ck[j] = (int)(lo & 0xFFFFu);
                    ci[j] = 3 - (int)((lo >> 16) & 0xFFFFu);
                }
            }
            psm_o[j] = peer[j] ? psm_v2x[ci[j] * K_SEL + ck[j]] : psm_ego;
        }
        *(float2*)&out[a * HW + p] = make_float2(psm_o[0], psm_o[1]);

#pragma unroll
        for (int r = 0; r < 7; ++r) {
            int rc = 2 * r + a;              // rm channel using anchor-a winner
            float rb = reg_b[rc];
            float rv0 = peer[0] ? rm_v2x[(ci[0] * 7 + r) * K_SEL + ck[0]]
                                : v[A_NUM + rc][0] + rb;
            float rv1 = peer[1] ? rm_v2x[(ci[1] * 7 + r) * K_SEL + ck[1]]
                                : v[A_NUM + rc][1] + rb;
            *(float2*)&out[RM_OFF + rc * HW + p] = make_float2(rv0, rv1);
        }
    }
}

// ---------------- launch ----------------
extern "C" void kernel_launch(void* const* d_in, const int* in_sizes, int n_in,
                              void* d_out, int out_size) {
    const float*  feat     = (const float*)d_in[0];   // [1,256,200,704] f32
    const float*  cls_w    = (const float*)d_in[1];   // [2,256]
    const float*  cls_b    = (const float*)d_in[2];   // [2]
    const float*  reg_w    = (const float*)d_in[3];   // [14,256]
    const float*  reg_b    = (const float*)d_in[4];   // [14]
    const float*  psm_v2x  = (const float*)d_in[5];   // [4,20000]
    const float*  rm_v2x   = (const float*)d_in[6];   // [4,140000]
    const float*  scores   = (const float*)d_in[7];   // [4,20000]
    const int*    mask_idx = (const int*)d_in[8];     // [4,20000]
    // d_in[9] = mask_reg_idx: derivable (f + r*A*H*W), unused.
    float* out = (float*)d_out;

    // zero the winner table via a graph memset node (no kernel launch cost)
    void* slots_ptr = nullptr;
    cudaGetSymbolAddress(&slots_ptr, g_slots);
    cudaMemsetAsync(slots_ptr, 0, NSLOT * sizeof(unsigned long long));

    k_scatter<<<(NC_NUM * K_SEL + 255) / 256, 256>>>(mask_idx, scores);

    k_main<<<HW / PX_BLK, THREADS>>>(feat, cls_w, cls_b, reg_w, reg_b,
                                     psm_v2x, rm_v2x, out);
}